// round 15
// baseline (speedup 1.0000x reference)
#include <cuda_runtime.h>
#include <cuda_fp16.h>
#include <cstdint>

#define NODES_MAX 100032
#define FEAT 128
#define BSTRIDE 136    // fp16 elems per smem A/B row (272B: ldmatrix conflict-free)
#define DSTRIDE 264    // fp16 elems per smem D-stage row (528B: 4-bank rotation/row)
#define BLOCK 512

// Per-node projections, fp16: g_H[n][o<128] = feat[n]@W1[o][0:128].T + b1[o]
//                             g_H[n][128+j] = feat[n]@W1[j][128:256].T
__device__ __half g_H[(size_t)NODES_MAX * 256];
// W2 pre-converted to fp16 pairs (64 half2 = 128 channels)
__device__ __half2 g_W2h[64];

// smem offsets in half elements: A double-buffered, B single, D staging
#define OFF_A0 0
#define OFF_A1 (128 * BSTRIDE)
#define OFF_B  (256 * BSTRIDE)
#define OFF_D  (512 * BSTRIDE)
#define SMEM_HALVES (512 * BSTRIDE + 128 * DSTRIDE)   // 103424 halves = 206848 B

__device__ __forceinline__ uint32_t smem_u32(const void* p) {
    uint32_t a;
    asm("{ .reg .u64 t; cvta.to.shared.u64 t, %1; cvt.u32.u64 %0, t; }" : "=r"(a) : "l"(p));
    return a;
}
__device__ __forceinline__ void ldsm_x4(uint32_t* r, uint32_t addr) {
    asm volatile("ldmatrix.sync.aligned.m8n8.x4.shared.b16 {%0,%1,%2,%3}, [%4];"
                 : "=r"(r[0]), "=r"(r[1]), "=r"(r[2]), "=r"(r[3]) : "r"(addr));
}
__device__ __forceinline__ void mma_f16(float* d, const uint32_t* a, const uint32_t* b) {
    asm volatile("mma.sync.aligned.m16n8k16.row.col.f32.f16.f16.f32 "
                 "{%0,%1,%2,%3}, {%4,%5,%6,%7}, {%8,%9}, {%0,%1,%2,%3};"
                 : "+f"(d[0]), "+f"(d[1]), "+f"(d[2]), "+f"(d[3])
                 : "r"(a[0]), "r"(a[1]), "r"(a[2]), "r"(a[3]), "r"(b[0]), "r"(b[1]));
}

// ---- A tile staging: prefetch fp32 into regs, convert+store later ----
__device__ __forceinline__ void prefetch_A(const float* __restrict__ feat, int node0,
                                           int n_nodes, int tid, float4* pf) {
    const float4* f4 = reinterpret_cast<const float4*>(feat);
    #pragma unroll
    for (int it = 0; it < 8; ++it) {
        int g = tid + it * BLOCK;        // float4 idx 0..4095 (128 rows x 32)
        int row = g >> 5, c4 = g & 31;
        int node = node0 + row;
        pf[it] = (node < n_nodes) ? f4[(size_t)node * 32 + c4]
                                  : make_float4(0.f, 0.f, 0.f, 0.f);
    }
}
__device__ __forceinline__ void store_A(__half* smem, uint32_t offA, int tid, const float4* pf) {
    #pragma unroll
    for (int it = 0; it < 8; ++it) {
        int g = tid + it * BLOCK;
        int row = g >> 5, c4 = g & 31;
        __half2 h0 = __floats2half2_rn(pf[it].x, pf[it].y);
        __half2 h1 = __floats2half2_rn(pf[it].z, pf[it].w);
        uint2 u;
        u.x = *reinterpret_cast<uint32_t*>(&h0);
        u.y = *reinterpret_cast<uint32_t*>(&h1);
        *reinterpret_cast<uint2*>(smem + offA + (uint32_t)row * BSTRIDE + c4 * 4) = u;
    }
}

// ---------------------------------------------------------------------------
// Tiny setup kernel: W2 fp32 -> half2 table (once per launch; 64 threads).
// ---------------------------------------------------------------------------
__global__ void cvt_w2_kernel(const float* __restrict__ W2) {
    int i = threadIdx.x;                 // 0..63
    g_W2h[i] = __floats2half2_rn(W2[2 * i], W2[2 * i + 1]);
}

// ---------------------------------------------------------------------------
// Persistent node-projection GEMM, fp16 HMMA, A double-buffered,
// per-warp-owned D staging, one syncthreads per tile. (Best: R12-R14, 33us.)
// Tile: 128 nodes x 256 outputs, K=128. 16 warps in 4(M) x 4(N), 32x64/warp.
// ---------------------------------------------------------------------------
__global__ void __launch_bounds__(BLOCK, 1)
node_mma_kernel(const float* __restrict__ feat,
                const float* __restrict__ W1,
                const float* __restrict__ b1,
                int n_nodes, int n_tiles) {
    extern __shared__ __half smem[];
    const uint32_t sbase = smem_u32(smem);
    const int tid = threadIdx.x;
    const int wid = tid >> 5;
    const int lane = tid & 31;

    float4 pf[8];
    prefetch_A(feat, blockIdx.x * 128, n_nodes, tid, pf);   // first tile, early

    // ---- Convert W1 -> B (fp16) once. B[o][k] = W1[o&127][(o>>7)*128+k] ----
    #pragma unroll 4
    for (int it = 0; it < 16; ++it) {
        int g = tid + it * BLOCK;            // float4 idx 0..8191 (256 rows x 32)
        int o = g >> 5, c4 = g & 31;
        float4 v = *reinterpret_cast<const float4*>(
            W1 + (size_t)(o & 127) * 256 + (o >> 7) * 128 + c4 * 4);
        __half2 h0 = __floats2half2_rn(v.x, v.y);
        __half2 h1 = __floats2half2_rn(v.z, v.w);
        uint2 u;
        u.x = *reinterpret_cast<uint32_t*>(&h0);
        u.y = *reinterpret_cast<uint32_t*>(&h1);
        *reinterpret_cast<uint2*>(smem + OFF_B + (uint32_t)o * BSTRIDE + c4 * 4) = u;
    }

    store_A(smem, OFF_A0, tid, pf);
    __syncthreads();

    const int m0 = (wid & 3) * 32;
    const int n0 = (wid >> 2) * 64;
    const int a_row = (lane & 15);
    const int a_col = (lane >> 4) * 8;
    const int b_row = ((lane >> 4) << 3) + (lane & 7);
    const int b_col = ((lane >> 3) & 1) * 8;
    const int tr = lane >> 2;
    const int tc = (lane & 3) * 2;
    const int r4 = lane >> 3;            // ep2: row-within-4 group
    const int ci = lane & 7;             // ep2: 16B col chunk

    int p = 0;
    for (int tile = blockIdx.x; tile < n_tiles; tile += gridDim.x) {
        const int next = tile + gridDim.x;
        if (next < n_tiles) prefetch_A(feat, next * 128, n_nodes, tid, pf);

        const uint32_t offA = p ? OFF_A1 : OFF_A0;
        const int node0 = tile * 128;

        float d[2][8][4];
        #pragma unroll
        for (int mt = 0; mt < 2; ++mt)
            #pragma unroll
            for (int nt = 0; nt < 8; ++nt)
                #pragma unroll
                for (int j = 0; j < 4; ++j) d[mt][nt][j] = 0.f;

        #pragma unroll
        for (int ks = 0; ks < 8; ++ks) {
            const int k = ks * 16;
            uint32_t af[2][4], bf[4][4];
            #pragma unroll
            for (int mt = 0; mt < 2; ++mt)
                ldsm_x4(af[mt], sbase + (offA + (uint32_t)(m0 + mt * 16 + a_row) * BSTRIDE + k + a_col) * 2);
            #pragma unroll
            for (int np = 0; np < 4; ++np)
                ldsm_x4(bf[np], sbase + (OFF_B + (uint32_t)(n0 + np * 16 + b_row) * BSTRIDE + k + b_col) * 2);
            #pragma unroll
            for (int mt = 0; mt < 2; ++mt)
                #pragma unroll
                for (int nt = 0; nt < 8; ++nt)
                    mma_f16(d[mt][nt], af[mt], &bf[nt >> 1][(nt & 1) * 2]);
        }

        // ---- Stage next A early: STS latency hides under epilogue-1 ----
        if (next < n_tiles) store_A(smem, p ? OFF_A0 : OFF_A1, tid, pf);

        // ---- Epilogue 1: bias + cvt -> D stage; warp-owned region only ----
        #pragma unroll
        for (int nt = 0; nt < 8; ++nt) {
            int col = n0 + nt * 8 + tc;
            float2 bias = make_float2(0.f, 0.f);
            if (col < 128) bias = *reinterpret_cast<const float2*>(b1 + col);
            #pragma unroll
            for (int mt = 0; mt < 2; ++mt) {
                int ra = m0 + mt * 16 + tr;          // local rows
                __half2 oa = __floats2half2_rn(d[mt][nt][0] + bias.x, d[mt][nt][1] + bias.y);
                __half2 ob = __floats2half2_rn(d[mt][nt][2] + bias.x, d[mt][nt][3] + bias.y);
                *reinterpret_cast<__half2*>(smem + OFF_D + (uint32_t)ra * DSTRIDE + col) = oa;
                *reinterpret_cast<__half2*>(smem + OFF_D + (uint32_t)(ra + 8) * DSTRIDE + col) = ob;
            }
        }
        __syncwarp();

        // ---- Epilogue 2: per-warp copy of own D region -> g_H ----
        #pragma unroll
        for (int k2 = 0; k2 < 8; ++k2) {
            int row = m0 + k2 * 4 + r4;
            int node = node0 + row;
            if (node < n_nodes) {
                uint4 v = *reinterpret_cast<const uint4*>(
                    smem + OFF_D + (uint32_t)row * DSTRIDE + n0 + ci * 8);
                *reinterpret_cast<uint4*>(g_H + (size_t)node * 256 + n0 + ci * 8) = v;
            }
        }

        __syncthreads();   // protects A double-buffer for next mainloop
        p ^= 1;
    }
}

// ---------------------------------------------------------------------------
// Kernel 2: per-edge score, 8 edges/warp. Block-staged indices (R14) +
// fp16 dot with pre-converted W2 (no float4 w ever live -> regs stay <=32).
// ---------------------------------------------------------------------------
#define EPW 8
#define EDGES_PER_BLK 64
__global__ void __launch_bounds__(256, 8)
edge_score_kernel(const int* __restrict__ src,
                  const int* __restrict__ dst,
                  const float* __restrict__ b2,
                  float* __restrict__ out,
                  int n_edges) {
    __shared__ int s_src[EDGES_PER_BLK];
    __shared__ int s_dst[EDGES_PER_BLK];

    const int tid = threadIdx.x;
    const int blk_e0 = blockIdx.x * EDGES_PER_BLK;

    // Stage 64 src + 64 dst indices, coalesced, clamped once here.
    if (tid < EDGES_PER_BLK)
        s_src[tid] = __ldg(src + min(blk_e0 + tid, n_edges - 1));
    else if (tid < 2 * EDGES_PER_BLK)
        s_dst[tid - EDGES_PER_BLK] = __ldg(dst + min(blk_e0 + tid - EDGES_PER_BLK, n_edges - 1));
    __syncthreads();

    const int warp = tid >> 5;
    const int lane = tid & 31;
    const int e0 = blk_e0 + warp * EPW;
    if (e0 >= n_edges) return;

    // W2 as two half2 regs (pre-converted; float4 never exists here).
    const uint2 wu = *reinterpret_cast<const uint2*>(g_W2h + lane * 2);
    const __half2 w01 = *reinterpret_cast<const __half2*>(&wu.x);
    const __half2 w23 = *reinterpret_cast<const __half2*>(&wu.y);
    const char* base = reinterpret_cast<const char*>(g_H);
    const uint32_t lb = (uint32_t)lane * 8u;

    uint32_t po[EPW], qo[EPW];
    #pragma unroll
    for (int j = 0; j < EPW; ++j) {
        po[j] = (uint32_t)s_src[warp * EPW + j] * 512u + lb;
        qo[j] = (uint32_t)s_dst[warp * EPW + j] * 512u + 256u + lb;
    }

    uint2 pu[EPW], qu[EPW];
    #pragma unroll
    for (int j = 0; j < EPW; ++j)
        pu[j] = *reinterpret_cast<const uint2*>(base + po[j]);
    #pragma unroll
    for (int j = 0; j < EPW; ++j)
        qu[j] = *reinterpret_cast<const uint2*>(base + qo[j]);

    const __half2 z2 = __float2half2_rn(0.f);
    float v[EPW];
    #pragma unroll
    for (int j = 0; j < EPW; ++j) {
        __half2 s0 = __hmax2(__hadd2(*reinterpret_cast<const __half2*>(&pu[j].x),
                                     *reinterpret_cast<const __half2*>(&qu[j].x)), z2);
        __half2 s1 = __hmax2(__hadd2(*reinterpret_cast<const __half2*>(&pu[j].y),
                                     *reinterpret_cast<const __half2*>(&qu[j].y)), z2);
        __half2 t = __hfma2(s0, w01, __hmul2(s1, w23));
        float2 tf = __half22float2(t);
        v[j] = tf.x + tf.y;
    }

    // Lane-specialized reduction: 8 sums over 32 lanes in 9 shuffles.
    const unsigned FULL = 0xffffffffu;
    bool h16 = lane & 16;
    float a0 = (h16 ? v[4] : v[0]) + __shfl_xor_sync(FULL, h16 ? v[0] : v[4], 16);
    float a1 = (h16 ? v[5] : v[1]) + __shfl_xor_sync(FULL, h16 ? v[1] : v[5], 16);
    float a2 = (h16 ? v[6] : v[2]) + __shfl_xor_sync(FULL, h16 ? v[2] : v[6], 16);
    float a3 = (h16 ? v[7] : v[3]) + __shfl_xor_sync(FULL, h16 ? v[3] : v[7], 16);
    bool h8 = lane & 8;
    float b0 = (h8 ? a2 : a0) + __shfl_xor_sync(FULL, h8 ? a0 : a2, 8);
    float b1v = (h8 ? a3 : a1) + __shfl_xor_sync(FULL, h8 ? a1 : a3, 8);
    bool h4 = lane & 4;
    float c = (h4 ? b1v : b0) + __shfl_xor_sync(FULL, h4 ? b0 : b1v, 4);
    c += __shfl_xor_sync(FULL, c, 2);
    c += __shfl_xor_sync(FULL, c, 1);
    int e = lane >> 2;
    if ((lane & 3) == 0 && e0 + e < n_edges)
        out[e0 + e] = c + __ldg(b2);
}

// ---------------------------------------------------------------------------
// kernel_launch — graph-capturable, allocation-free.
// Inputs: feature[f32 N*128], src[i32 E], dst[i32 E],
//         W1[f32 128*256], b1[f32 128], W2[f32 128], b2[f32 1]
// ---------------------------------------------------------------------------
extern "C" void kernel_launch(void* const* d_in, const int* in_sizes, int n_in,
                              void* d_out, int out_size) {
    const float* feat = (const float*)d_in[0];
    const int*   src  = (const int*)d_in[1];
    const int*   dst  = (const int*)d_in[2];
    const float* W1   = (const float*)d_in[3];
    const float* b1   = (const float*)d_in[4];
    const float* W2   = (const float*)d_in[5];
    const float* b2   = (const float*)d_in[6];
    float*       out  = (float*)d_out;

    int n_nodes = in_sizes[0] / FEAT;
    int n_edges = in_sizes[1];
    int n_tiles = (n_nodes + 127) / 128;

    const int smem_bytes = SMEM_HALVES * 2;   // 206848 B
    cudaFuncSetAttribute(node_mma_kernel,
                         cudaFuncAttributeMaxDynamicSharedMemorySize, smem_bytes);

    cvt_w2_kernel<<<1, 64>>>(W2);

    int grid = n_tiles < 148 ? n_tiles : 148;
    node_mma_kernel<<<grid, BLOCK, smem_bytes>>>(feat, W1, b1, n_nodes, n_tiles);

    int blocks = (n_edges + EDGES_PER_BLK - 1) / EDGES_PER_BLK;
    edge_score_kernel<<<blocks, 256>>>(src, dst, b2, out, n_edges);
}

// round 16
// speedup vs baseline: 1.0238x; 1.0238x over previous
#include <cuda_runtime.h>
#include <cuda_fp16.h>
#include <cstdint>

#define NODES_MAX 100032
#define FEAT 128
#define BSTRIDE 136    // fp16 elems per smem A/B row (272B: ldmatrix conflict-free)
#define DSTRIDE 264    // fp16 elems per smem D-stage row (528B: 4-bank rotation/row)
#define BLOCK 512

// Per-node projections, fp16: g_H[n][o<128] = feat[n]@W1[o][0:128].T + b1[o]
//                             g_H[n][128+j] = feat[n]@W1[j][128:256].T
__device__ __half g_H[(size_t)NODES_MAX * 256];
// W2 pre-converted to fp16 pairs (64 half2 = 128 channels); written by
// node_mma_kernel block 0, consumed by edge_score_kernel (same stream, ordered).
__device__ __half2 g_W2h[64];

// smem offsets in half elements: A double-buffered, B single, D staging
#define OFF_A0 0
#define OFF_A1 (128 * BSTRIDE)
#define OFF_B  (256 * BSTRIDE)
#define OFF_D  (512 * BSTRIDE)
#define SMEM_HALVES (512 * BSTRIDE + 128 * DSTRIDE)   // 103424 halves = 206848 B

__device__ __forceinline__ uint32_t smem_u32(const void* p) {
    uint32_t a;
    asm("{ .reg .u64 t; cvta.to.shared.u64 t, %1; cvt.u32.u64 %0, t; }" : "=r"(a) : "l"(p));
    return a;
}
__device__ __forceinline__ void ldsm_x4(uint32_t* r, uint32_t addr) {
    asm volatile("ldmatrix.sync.aligned.m8n8.x4.shared.b16 {%0,%1,%2,%3}, [%4];"
                 : "=r"(r[0]), "=r"(r[1]), "=r"(r[2]), "=r"(r[3]) : "r"(addr));
}
__device__ __forceinline__ void mma_f16(float* d, const uint32_t* a, const uint32_t* b) {
    asm volatile("mma.sync.aligned.m16n8k16.row.col.f32.f16.f16.f32 "
                 "{%0,%1,%2,%3}, {%4,%5,%6,%7}, {%8,%9}, {%0,%1,%2,%3};"
                 : "+f"(d[0]), "+f"(d[1]), "+f"(d[2]), "+f"(d[3])
                 : "r"(a[0]), "r"(a[1]), "r"(a[2]), "r"(a[3]), "r"(b[0]), "r"(b[1]));
}

// ---- A tile staging: prefetch fp32 into regs, convert+store later ----
__device__ __forceinline__ void prefetch_A(const float* __restrict__ feat, int node0,
                                           int n_nodes, int tid, float4* pf) {
    const float4* f4 = reinterpret_cast<const float4*>(feat);
    #pragma unroll
    for (int it = 0; it < 8; ++it) {
        int g = tid + it * BLOCK;        // float4 idx 0..4095 (128 rows x 32)
        int row = g >> 5, c4 = g & 31;
        int node = node0 + row;
        pf[it] = (node < n_nodes) ? f4[(size_t)node * 32 + c4]
                                  : make_float4(0.f, 0.f, 0.f, 0.f);
    }
}
__device__ __forceinline__ void store_A(__half* smem, uint32_t offA, int tid, const float4* pf) {
    #pragma unroll
    for (int it = 0; it < 8; ++it) {
        int g = tid + it * BLOCK;
        int row = g >> 5, c4 = g & 31;
        __half2 h0 = __floats2half2_rn(pf[it].x, pf[it].y);
        __half2 h1 = __floats2half2_rn(pf[it].z, pf[it].w);
        uint2 u;
        u.x = *reinterpret_cast<uint32_t*>(&h0);
        u.y = *reinterpret_cast<uint32_t*>(&h1);
        *reinterpret_cast<uint2*>(smem + offA + (uint32_t)row * BSTRIDE + c4 * 4) = u;
    }
}

// ---------------------------------------------------------------------------
// Persistent node-projection GEMM, fp16 HMMA, A double-buffered,
// per-warp-owned D staging, one syncthreads per tile. (Best: R12-R14, ~33.5us.)
// Block 0 also converts W2 -> g_W2h in the prologue (replaces the 3.9us
// separate cvt kernel from R15).
// Tile: 128 nodes x 256 outputs, K=128. 16 warps in 4(M) x 4(N), 32x64/warp.
// ---------------------------------------------------------------------------
__global__ void __launch_bounds__(BLOCK, 1)
node_mma_kernel(const float* __restrict__ feat,
                const float* __restrict__ W1,
                const float* __restrict__ b1,
                const float* __restrict__ W2,
                int n_nodes, int n_tiles) {
    extern __shared__ __half smem[];
    const uint32_t sbase = smem_u32(smem);
    const int tid = threadIdx.x;
    const int wid = tid >> 5;
    const int lane = tid & 31;

    // ---- W2 -> half2 table (block 0 only; edge kernel runs after us) ----
    if (blockIdx.x == 0 && tid < 64)
        g_W2h[tid] = __floats2half2_rn(W2[2 * tid], W2[2 * tid + 1]);

    float4 pf[8];
    prefetch_A(feat, blockIdx.x * 128, n_nodes, tid, pf);   // first tile, early

    // ---- Convert W1 -> B (fp16) once. B[o][k] = W1[o&127][(o>>7)*128+k] ----
    #pragma unroll 4
    for (int it = 0; it < 16; ++it) {
        int g = tid + it * BLOCK;            // float4 idx 0..8191 (256 rows x 32)
        int o = g >> 5, c4 = g & 31;
        float4 v = *reinterpret_cast<const float4*>(
            W1 + (size_t)(o & 127) * 256 + (o >> 7) * 128 + c4 * 4);
        __half2 h0 = __floats2half2_rn(v.x, v.y);
        __half2 h1 = __floats2half2_rn(v.z, v.w);
        uint2 u;
        u.x = *reinterpret_cast<uint32_t*>(&h0);
        u.y = *reinterpret_cast<uint32_t*>(&h1);
        *reinterpret_cast<uint2*>(smem + OFF_B + (uint32_t)o * BSTRIDE + c4 * 4) = u;
    }

    store_A(smem, OFF_A0, tid, pf);
    __syncthreads();

    const int m0 = (wid & 3) * 32;
    const int n0 = (wid >> 2) * 64;
    const int a_row = (lane & 15);
    const int a_col = (lane >> 4) * 8;
    const int b_row = ((lane >> 4) << 3) + (lane & 7);
    const int b_col = ((lane >> 3) & 1) * 8;
    const int tr = lane >> 2;
    const int tc = (lane & 3) * 2;
    const int r4 = lane >> 3;            // ep2: row-within-4 group
    const int ci = lane & 7;             // ep2: 16B col chunk

    int p = 0;
    for (int tile = blockIdx.x; tile < n_tiles; tile += gridDim.x) {
        const int next = tile + gridDim.x;
        if (next < n_tiles) prefetch_A(feat, next * 128, n_nodes, tid, pf);

        const uint32_t offA = p ? OFF_A1 : OFF_A0;
        const int node0 = tile * 128;

        float d[2][8][4];
        #pragma unroll
        for (int mt = 0; mt < 2; ++mt)
            #pragma unroll
            for (int nt = 0; nt < 8; ++nt)
                #pragma unroll
                for (int j = 0; j < 4; ++j) d[mt][nt][j] = 0.f;

        #pragma unroll
        for (int ks = 0; ks < 8; ++ks) {
            const int k = ks * 16;
            uint32_t af[2][4], bf[4][4];
            #pragma unroll
            for (int mt = 0; mt < 2; ++mt)
                ldsm_x4(af[mt], sbase + (offA + (uint32_t)(m0 + mt * 16 + a_row) * BSTRIDE + k + a_col) * 2);
            #pragma unroll
            for (int np = 0; np < 4; ++np)
                ldsm_x4(bf[np], sbase + (OFF_B + (uint32_t)(n0 + np * 16 + b_row) * BSTRIDE + k + b_col) * 2);
            #pragma unroll
            for (int mt = 0; mt < 2; ++mt)
                #pragma unroll
                for (int nt = 0; nt < 8; ++nt)
                    mma_f16(d[mt][nt], af[mt], &bf[nt >> 1][(nt & 1) * 2]);
        }

        // ---- Stage next A early: STS latency hides under epilogue-1 ----
        if (next < n_tiles) store_A(smem, p ? OFF_A0 : OFF_A1, tid, pf);

        // ---- Epilogue 1: bias + cvt -> D stage; warp-owned region only ----
        #pragma unroll
        for (int nt = 0; nt < 8; ++nt) {
            int col = n0 + nt * 8 + tc;
            float2 bias = make_float2(0.f, 0.f);
            if (col < 128) bias = *reinterpret_cast<const float2*>(b1 + col);
            #pragma unroll
            for (int mt = 0; mt < 2; ++mt) {
                int ra = m0 + mt * 16 + tr;          // local rows
                __half2 oa = __floats2half2_rn(d[mt][nt][0] + bias.x, d[mt][nt][1] + bias.y);
                __half2 ob = __floats2half2_rn(d[mt][nt][2] + bias.x, d[mt][nt][3] + bias.y);
                *reinterpret_cast<__half2*>(smem + OFF_D + (uint32_t)ra * DSTRIDE + col) = oa;
                *reinterpret_cast<__half2*>(smem + OFF_D + (uint32_t)(ra + 8) * DSTRIDE + col) = ob;
            }
        }
        __syncwarp();

        // ---- Epilogue 2: per-warp copy of own D region -> g_H ----
        #pragma unroll
        for (int k2 = 0; k2 < 8; ++k2) {
            int row = m0 + k2 * 4 + r4;
            int node = node0 + row;
            if (node < n_nodes) {
                uint4 v = *reinterpret_cast<const uint4*>(
                    smem + OFF_D + (uint32_t)row * DSTRIDE + n0 + ci * 8);
                *reinterpret_cast<uint4*>(g_H + (size_t)node * 256 + n0 + ci * 8) = v;
            }
        }

        __syncthreads();   // protects A double-buffer for next mainloop
        p ^= 1;
    }
}

// ---------------------------------------------------------------------------
// Kernel 2: per-edge score, 8 edges/warp. Block-staged indices (R14) +
// fp16 dot with pre-converted W2 (no float4 w ever live -> regs stay <=32).
// (Exact R15 body — measured ~30.1us.)
// ---------------------------------------------------------------------------
#define EPW 8
#define EDGES_PER_BLK 64
__global__ void __launch_bounds__(256, 8)
edge_score_kernel(const int* __restrict__ src,
                  const int* __restrict__ dst,
                  const float* __restrict__ b2,
                  float* __restrict__ out,
                  int n_edges) {
    __shared__ int s_src[EDGES_PER_BLK];
    __shared__ int s_dst[EDGES_PER_BLK];

    const int tid = threadIdx.x;
    const int blk_e0 = blockIdx.x * EDGES_PER_BLK;

    // Stage 64 src + 64 dst indices, coalesced, clamped once here.
    if (tid < EDGES_PER_BLK)
        s_src[tid] = __ldg(src + min(blk_e0 + tid, n_edges - 1));
    else if (tid < 2 * EDGES_PER_BLK)
        s_dst[tid - EDGES_PER_BLK] = __ldg(dst + min(blk_e0 + tid - EDGES_PER_BLK, n_edges - 1));
    __syncthreads();

    const int warp = tid >> 5;
    const int lane = tid & 31;
    const int e0 = blk_e0 + warp * EPW;
    if (e0 >= n_edges) return;

    // W2 as two half2 regs (pre-converted; float4 never exists here).
    const uint2 wu = *reinterpret_cast<const uint2*>(g_W2h + lane * 2);
    const __half2 w01 = *reinterpret_cast<const __half2*>(&wu.x);
    const __half2 w23 = *reinterpret_cast<const __half2*>(&wu.y);
    const char* base = reinterpret_cast<const char*>(g_H);
    const uint32_t lb = (uint32_t)lane * 8u;

    uint32_t po[EPW], qo[EPW];
    #pragma unroll
    for (int j = 0; j < EPW; ++j) {
        po[j] = (uint32_t)s_src[warp * EPW + j] * 512u + lb;
        qo[j] = (uint32_t)s_dst[warp * EPW + j] * 512u + 256u + lb;
    }

    uint2 pu[EPW], qu[EPW];
    #pragma unroll
    for (int j = 0; j < EPW; ++j)
        pu[j] = *reinterpret_cast<const uint2*>(base + po[j]);
    #pragma unroll
    for (int j = 0; j < EPW; ++j)
        qu[j] = *reinterpret_cast<const uint2*>(base + qo[j]);

    const __half2 z2 = __float2half2_rn(0.f);
    float v[EPW];
    #pragma unroll
    for (int j = 0; j < EPW; ++j) {
        __half2 s0 = __hmax2(__hadd2(*reinterpret_cast<const __half2*>(&pu[j].x),
                                     *reinterpret_cast<const __half2*>(&qu[j].x)), z2);
        __half2 s1 = __hmax2(__hadd2(*reinterpret_cast<const __half2*>(&pu[j].y),
                                     *reinterpret_cast<const __half2*>(&qu[j].y)), z2);
        __half2 t = __hfma2(s0, w01, __hmul2(s1, w23));
        float2 tf = __half22float2(t);
        v[j] = tf.x + tf.y;
    }

    // Lane-specialized reduction: 8 sums over 32 lanes in 9 shuffles.
    const unsigned FULL = 0xffffffffu;
    bool h16 = lane & 16;
    float a0 = (h16 ? v[4] : v[0]) + __shfl_xor_sync(FULL, h16 ? v[0] : v[4], 16);
    float a1 = (h16 ? v[5] : v[1]) + __shfl_xor_sync(FULL, h16 ? v[1] : v[5], 16);
    float a2 = (h16 ? v[6] : v[2]) + __shfl_xor_sync(FULL, h16 ? v[2] : v[6], 16);
    float a3 = (h16 ? v[7] : v[3]) + __shfl_xor_sync(FULL, h16 ? v[3] : v[7], 16);
    bool h8 = lane & 8;
    float b0 = (h8 ? a2 : a0) + __shfl_xor_sync(FULL, h8 ? a0 : a2, 8);
    float b1v = (h8 ? a3 : a1) + __shfl_xor_sync(FULL, h8 ? a1 : a3, 8);
    bool h4 = lane & 4;
    float c = (h4 ? b1v : b0) + __shfl_xor_sync(FULL, h4 ? b0 : b1v, 4);
    c += __shfl_xor_sync(FULL, c, 2);
    c += __shfl_xor_sync(FULL, c, 1);
    int e = lane >> 2;
    if ((lane & 3) == 0 && e0 + e < n_edges)
        out[e0 + e] = c + __ldg(b2);
}

// ---------------------------------------------------------------------------
// kernel_launch — graph-capturable, allocation-free.
// Inputs: feature[f32 N*128], src[i32 E], dst[i32 E],
//         W1[f32 128*256], b1[f32 128], W2[f32 128], b2[f32 1]
// ---------------------------------------------------------------------------
extern "C" void kernel_launch(void* const* d_in, const int* in_sizes, int n_in,
                              void* d_out, int out_size) {
    const float* feat = (const float*)d_in[0];
    const int*   src  = (const int*)d_in[1];
    const int*   dst  = (const int*)d_in[2];
    const float* W1   = (const float*)d_in[3];
    const float* b1   = (const float*)d_in[4];
    const float* W2   = (const float*)d_in[5];
    const float* b2   = (const float*)d_in[6];
    float*       out  = (float*)d_out;

    int n_nodes = in_sizes[0] / FEAT;
    int n_edges = in_sizes[1];
    int n_tiles = (n_nodes + 127) / 128;

    const int smem_bytes = SMEM_HALVES * 2;   // 206848 B
    cudaFuncSetAttribute(node_mma_kernel,
                         cudaFuncAttributeMaxDynamicSharedMemorySize, smem_bytes);

    int grid = n_tiles < 148 ? n_tiles : 148;
    node_mma_kernel<<<grid, BLOCK, smem_bytes>>>(feat, W1, b1, W2, n_nodes, n_tiles);

    int blocks = (n_edges + EDGES_PER_BLK - 1) / EDGES_PER_BLK;
    edge_score_kernel<<<blocks, 256>>>(src, dst, b2, out, n_edges);
}